// round 4
// baseline (speedup 1.0000x reference)
#include <cuda_runtime.h>
#include <math.h>

#define DEPTH 24
#define DM    192
#define DI    384
#define DS    16
#define DR    12
#define BATCH 4
#define LSEQ  401
#define NCLS  22
#define XD    44
#define EPSV  1e-5f
#define NC    31
#define CL    13
#define ROWS  (BATCH*LSEQ)     // 1604
#define ROWS2 (2*BATCH*LSEQ)   // 3208
#define NBLK  296

// ---------------- scratch ----------------------------------------------------
__device__ float g_res [ROWS*DM];
__device__ float g_hn  [ROWS*DM];
__device__ float g_xz  [ROWS*2*DI];
__device__ float g_xx  [ROWS2*DI];
__device__ float g_dbl [ROWS2*XD];
__device__ float g_y   [ROWS2*DI];
__device__ float g_Aexp[2*DEPTH*DI*DS];
__device__ int   g_Aflag[2*DEPTH*DI];
__device__ float g_hloc[2*BATCH*NC*DS*DI];
__device__ float g_S   [2*BATCH*NC*DI];
__device__ unsigned g_arrive[NBLK];
__device__ unsigned g_release;

__device__ __forceinline__ float siluf(float x) { return x / (1.f + __expf(-x)); }
__device__ __forceinline__ float softplusf(float x) {
    return x > 20.f ? x : log1pf(__expf(x));
}

// ---------------- global barrier (monotonic generation) ----------------------
__device__ __forceinline__ void gbar(unsigned gen) {
    __syncthreads();
    if (blockIdx.x == 0) {
        __threadfence();
        for (int i = 1 + (int)threadIdx.x; i < NBLK; i += 256) {
            while ((int)(*(volatile unsigned*)&g_arrive[i] - gen) < 0) __nanosleep(40);
        }
        __threadfence();
        __syncthreads();
        if (threadIdx.x == 0) *(volatile unsigned*)&g_release = gen;
    } else {
        if (threadIdx.x == 0) {
            __threadfence();
            *(volatile unsigned*)&g_arrive[blockIdx.x] = gen;
            while ((int)(*(volatile unsigned*)&g_release - gen) < 0) __nanosleep(40);
            __threadfence();
        }
        __syncthreads();
    }
}

// ---------------- prep: A = -exp(A_log); detect geometric structure ----------
__global__ void k_prepA(const float* __restrict__ Alog, const float* __restrict__ Ablog) {
    int i = blockIdx.x * blockDim.x + threadIdx.x;
    if (i >= 2 * DEPTH * DI) return;
    int dir = i / (DEPTH * DI);
    int rest = i - dir * (DEPTH * DI);
    const float* src = (dir ? Ablog : Alog) + (size_t)rest * DS;
    float A[DS];
#pragma unroll
    for (int n = 0; n < DS; n++) A[n] = -__expf(src[n]);
    float A0 = A[0];
    bool ok = true;
#pragma unroll
    for (int n = 1; n < DS; n++) {
        float tgt = (float)(n + 1) * A0;
        ok = ok && (fabsf(A[n] - tgt) <= 1e-4f * fabsf(tgt) + 1e-30f);
    }
#pragma unroll
    for (int n = 0; n < DS; n++) g_Aexp[(size_t)i * DS + n] = A[n];
    g_Aflag[i] = ok ? 1 : 0;
}

// =============================================================================
// The whole network in one persistent kernel.
// =============================================================================
__global__ __launch_bounds__(256, 2)
void k_net(const float* __restrict__ x,   const float* __restrict__ pew,
           const float* __restrict__ peb, const float* __restrict__ cls,
           const float* __restrict__ pos, const float* __restrict__ norm_w,
           const float* __restrict__ ipw, const float* __restrict__ cw,
           const float* __restrict__ cb,  const float* __restrict__ xpw,
           const float* __restrict__ dtw, const float* __restrict__ dtb,
           const float* __restrict__ Dp,  const float* __restrict__ opw,
           const float* __restrict__ nfw, const float* __restrict__ hw,
           const float* __restrict__ hb,  float* __restrict__ out) {
    const int bid = blockIdx.x;
    const int tid = threadIdx.x;
    unsigned gen = *(volatile unsigned*)&g_release;   // monotonic base across replays
    __shared__ float sm[3400];
    __shared__ float red2[8];

    // ================= stage: patch embed + cls + pos + layer-0 norm =========
    for (int p = bid; p < ROWS; p += NBLK) {
        int b = p / LSEQ, t = p % LSEQ;
        float v = 0.f;
        if (t == 0) {
            if (tid < DM) v = cls[tid] + pos[tid];
        } else {
            int pp = t - 1, ph = pp / 200, pw = pp % 200;
            sm[tid] = x[(size_t)b * 32 * 3200 + (size_t)(ph * 16 + tid / 16) * 3200
                        + pw * 16 + (tid % 16)];
            __syncthreads();
            if (tid < DM) {
                float acc = peb[tid];
                const float* wc = pew + (size_t)tid * 256;
#pragma unroll 8
                for (int i = 0; i < 256; i++) acc = fmaf(sm[i], __ldg(wc + i), acc);
                v = acc + pos[(size_t)t * DM + tid];
            }
        }
        float u = 2.f * v;                     // residual after layer-0 add
        float s = (tid < DM) ? u * u : 0.f;
#pragma unroll
        for (int ofs = 16; ofs > 0; ofs >>= 1) s += __shfl_xor_sync(0xffffffffu, s, ofs);
        if ((tid & 31) == 0 && tid < DM) red2[tid >> 5] = s;
        __syncthreads();
        if (tid < DM) {
            float tot = red2[0] + red2[1] + red2[2] + red2[3] + red2[4] + red2[5];
            float rs = rsqrtf(tot / (float)DM + EPSV);
            size_t o = (size_t)p * DM + tid;
            g_res[o] = u;
            g_hn[o]  = u * rs * norm_w[tid];
        }
        __syncthreads();
    }
    gbar(++gen);

    // ================= layer loop ============================================
    for (int l = 0; l < DEPTH; l++) {
        const float* ipw_l = ipw + (size_t)l * 2 * DI * DM;
        const float* cw_l  = cw  + (size_t)l * DI * 4;
        const float* cb_l  = cb  + (size_t)l * DI;
        const float* xpw_l = xpw + (size_t)l * XD * DI;
        const float* dtw_l = dtw + (size_t)l * DI * DR;
        const float* dtb_l = dtb + (size_t)l * DI;
        const float* Dp_l  = Dp  + (size_t)l * DI;
        const float* opw_l = opw + (size_t)l * DM * DI;
        const float* nw_next = (l == DEPTH - 1) ? nfw : (norm_w + (size_t)(l + 1) * DM);

        // ---- S2: in_proj GEMM  xz[1604,768] = hn[1604,192] @ ipw^T ----------
        {
            float* As = sm;                  // [16][68]
            float* Ws = sm + 16 * 68;        // [16][68]
            for (int tile = bid; tile < 26 * 12; tile += NBLK) {
                int bx = tile % 12, by = tile / 12;
                int row0 = by * 64, col0 = bx * 64;
                float acc[4][4];
#pragma unroll
                for (int i = 0; i < 4; i++)
#pragma unroll
                    for (int j = 0; j < 4; j++) acc[i][j] = 0.f;
                int m = tid >> 2, kq = tid & 3;
                for (int k0 = 0; k0 < DM; k0 += 16) {
                    float4 va = make_float4(0.f, 0.f, 0.f, 0.f);
                    if (row0 + m < ROWS)
                        va = __ldg((const float4*)(g_hn + (size_t)(row0 + m) * DM + k0 + kq * 4));
                    As[(kq * 4 + 0) * 68 + m] = va.x; As[(kq * 4 + 1) * 68 + m] = va.y;
                    As[(kq * 4 + 2) * 68 + m] = va.z; As[(kq * 4 + 3) * 68 + m] = va.w;
                    float4 vw = __ldg((const float4*)(ipw_l + (size_t)(col0 + m) * DM + k0 + kq * 4));
                    Ws[(kq * 4 + 0) * 68 + m] = vw.x; Ws[(kq * 4 + 1) * 68 + m] = vw.y;
                    Ws[(kq * 4 + 2) * 68 + m] = vw.z; Ws[(kq * 4 + 3) * 68 + m] = vw.w;
                    __syncthreads();
                    int ty = tid / 16, tx = tid % 16;
#pragma unroll
                    for (int k = 0; k < 16; k++) {
                        float ra[4], rb[4];
#pragma unroll
                        for (int i = 0; i < 4; i++) ra[i] = As[k * 68 + ty * 4 + i];
#pragma unroll
                        for (int j = 0; j < 4; j++) rb[j] = Ws[k * 68 + tx * 4 + j];
#pragma unroll
                        for (int i = 0; i < 4; i++)
#pragma unroll
                            for (int j = 0; j < 4; j++)
                                acc[i][j] = fmaf(ra[i], rb[j], acc[i][j]);
                    }
                    __syncthreads();
                }
                int ty = tid / 16, tx = tid % 16;
#pragma unroll
                for (int i = 0; i < 4; i++) {
                    int r = row0 + ty * 4 + i;
                    if (r >= ROWS) continue;
#pragma unroll
                    for (int j = 0; j < 4; j++)
                        g_xz[(size_t)r * 2 * DI + col0 + tx * 4 + j] = acc[i][j];
                }
            }
        }
        gbar(++gen);

        // ---- S3: causal depthwise conv + silu (both dirs) -------------------
        for (int p = bid; p < ROWS2; p += NBLK) {
            int dir = p / ROWS;
            int rem = p - dir * ROWS;
            int b = rem / LSEQ, t = rem % LSEQ;
#pragma unroll
            for (int u = 0; u < 2; u++) {
                int d = tid + u * 256;
                if (d < DI) {
                    float4 w4 = __ldg((const float4*)(cw_l + d * 4));
                    float s = cb_l[d];
                    const float* xzb = g_xz + (size_t)b * LSEQ * 2 * DI + d;
                    if (dir == 0) {
                        if (t >= 3) s = fmaf(w4.x, xzb[(size_t)(t - 3) * 2 * DI], s);
                        if (t >= 2) s = fmaf(w4.y, xzb[(size_t)(t - 2) * 2 * DI], s);
                        if (t >= 1) s = fmaf(w4.z, xzb[(size_t)(t - 1) * 2 * DI], s);
                        s = fmaf(w4.w, xzb[(size_t)t * 2 * DI], s);
                    } else {
                        int base = LSEQ - 1 - t;
                        s = fmaf(w4.w, xzb[(size_t)base * 2 * DI], s);
                        if (t >= 1) s = fmaf(w4.z, xzb[(size_t)(base + 1) * 2 * DI], s);
                        if (t >= 2) s = fmaf(w4.y, xzb[(size_t)(base + 2) * 2 * DI], s);
                        if (t >= 3) s = fmaf(w4.x, xzb[(size_t)(base + 3) * 2 * DI], s);
                    }
                    g_xx[(size_t)p * DI + d] = siluf(s);
                }
            }
        }
        gbar(++gen);

        // ---- S4: dbl GEMM  dbl[3208,44] = xx @ xpw^T ------------------------
        {
            float* As = sm;                // [16][20]
            float* Ws = sm + 16 * 20;      // [16][52]
            for (int tile = bid; tile < 201; tile += NBLK) {
                int row0 = tile * 16;
                float acc[3] = {0.f, 0.f, 0.f};
                for (int k0 = 0; k0 < DI; k0 += 16) {
                    if (tid < 64) {
                        int m = tid >> 2, kq = tid & 3;
                        float4 v = make_float4(0.f, 0.f, 0.f, 0.f);
                        if (row0 + m < ROWS2)
                            v = __ldg((const float4*)(g_xx + (size_t)(row0 + m) * DI + k0 + kq * 4));
                        As[(kq * 4 + 0) * 20 + m] = v.x; As[(kq * 4 + 1) * 20 + m] = v.y;
                        As[(kq * 4 + 2) * 20 + m] = v.z; As[(kq * 4 + 3) * 20 + m] = v.w;
                    } else {
                        int i = tid - 64;          // 0..191
                        int n = i >> 2, kq = i & 3;
                        float4 v = make_float4(0.f, 0.f, 0.f, 0.f);
                        if (n < XD)
                            v = __ldg((const float4*)(xpw_l + (size_t)n * DI + k0 + kq * 4));
                        Ws[(kq * 4 + 0) * 52 + n] = v.x; Ws[(kq * 4 + 1) * 52 + n] = v.y;
                        Ws[(kq * 4 + 2) * 52 + n] = v.z; Ws[(kq * 4 + 3) * 52 + n] = v.w;
                    }
                    __syncthreads();
                    int ty = tid / 16, tx = tid % 16;
#pragma unroll
                    for (int k = 0; k < 16; k++) {
                        float ra = As[k * 20 + ty];
#pragma unroll
                        for (int j = 0; j < 3; j++)
                            acc[j] = fmaf(ra, Ws[k * 52 + tx * 3 + j], acc[j]);
                    }
                    __syncthreads();
                }
                int ty = tid / 16, tx = tid % 16;
                int r = row0 + ty;
                if (r < ROWS2) {
#pragma unroll
                    for (int j = 0; j < 3; j++) {
                        int n = tx * 3 + j;
                        if (n < XD) g_dbl[(size_t)r * XD + n] = acc[j];
                    }
                }
            }
        }
        gbar(++gen);

        // ---- S5: scanA (chunk-local, dt_proj fused, dbl row in smem) --------
        if (bid < 2 * BATCH * NC) {
            int dir = bid / (BATCH * NC);
            int rem = bid - dir * (BATCH * NC);
            int b = rem / NC, c = rem % NC;
            size_t r0 = ((size_t)dir * BATCH + b) * LSEQ;
            int t0 = c * CL, t1 = min(LSEQ, t0 + CL);

            float wdt[2][12], db0[2], Dd[2], A0[2];
            int flag[2];
            const float* Ap[2];
            float h[2][16], S[2];
#pragma unroll
            for (int u = 0; u < 2; u++) {
                int d = tid + u * 256;
                S[u] = 0.f;
#pragma unroll
                for (int n = 0; n < DS; n++) h[u][n] = 0.f;
                if (d < DI) {
                    Ap[u] = g_Aexp + (((size_t)dir * DEPTH + l) * DI + d) * DS;
                    A0[u] = Ap[u][0];
                    flag[u] = g_Aflag[((size_t)dir * DEPTH + l) * DI + d];
#pragma unroll
                    for (int j = 0; j < DR; j++) wdt[u][j] = __ldg(dtw_l + (size_t)d * DR + j);
                    db0[u] = dtb_l[d]; Dd[u] = Dp_l[d];
                }
            }
            if (tid < 11)
                ((float4*)sm)[tid] = __ldg((const float4*)(g_dbl + (r0 + t0) * XD) + tid);
            __syncthreads();
            for (int t = t0; t < t1; t++) {
                const float* cur = sm + (t & 1) * 44;
                if (t + 1 < t1 && tid < 11)
                    ((float4*)(sm + ((t + 1) & 1) * 44))[tid] =
                        __ldg((const float4*)(g_dbl + (r0 + t + 1) * XD) + tid);
#pragma unroll
                for (int u = 0; u < 2; u++) {
                    int d = tid + u * 256;
                    if (d < DI) {
                        float dtr = db0[u];
#pragma unroll
                        for (int j = 0; j < DR; j++) dtr = fmaf(cur[j], wdt[u][j], dtr);
                        float dt = softplusf(dtr);
                        float xv = g_xx[(r0 + t) * DI + d];
                        float dtx = dt * xv;
                        S[u] += dt;
                        float acc = 0.f;
                        if (flag[u]) {
                            float e = __expf(dt * A0[u]);
                            float p = e;
#pragma unroll
                            for (int n = 0; n < DS; n++) {
                                h[u][n] = fmaf(p, h[u][n], dtx * cur[12 + n]);
                                acc = fmaf(h[u][n], cur[28 + n], acc);
                                p *= e;
                            }
                        } else {
#pragma unroll
                            for (int n = 0; n < DS; n++) {
                                float a = __expf(dt * __ldg(Ap[u] + n));
                                h[u][n] = fmaf(a, h[u][n], dtx * cur[12 + n]);
                                acc = fmaf(h[u][n], cur[28 + n], acc);
                            }
                        }
                        g_y[(r0 + t) * DI + d] = acc + xv * Dd[u];
                    }
                }
                __syncthreads();
            }
            size_t cb_ = ((size_t)dir * BATCH + b) * NC + c;
#pragma unroll
            for (int u = 0; u < 2; u++) {
                int d = tid + u * 256;
                if (d < DI) {
#pragma unroll
                    for (int n = 0; n < DS; n++)
                        g_hloc[(cb_ * DS + n) * DI + d] = h[u][n];
                    g_S[cb_ * DI + d] = S[u];
                }
            }
        }
        gbar(++gen);

        // ---- S6: scanC (carry reconstruction + fixup) -----------------------
        if (bid < 2 * BATCH * (NC - 1)) {
            int dir = bid / (BATCH * (NC - 1));
            int rem = bid - dir * (BATCH * (NC - 1));
            int b = rem / (NC - 1), c = rem % (NC - 1) + 1;
            size_t r0 = ((size_t)dir * BATCH + b) * LSEQ;
            size_t cb0 = ((size_t)dir * BATCH + b) * NC;
            int t0 = c * CL, t1 = min(LSEQ, t0 + CL);

            float wdt[2][12], db0[2], A0[2];
            int flag[2];
            const float* Ap[2];
            float g[2][16];
#pragma unroll
            for (int u = 0; u < 2; u++) {
                int d = tid + u * 256;
#pragma unroll
                for (int n = 0; n < DS; n++) g[u][n] = 0.f;
                if (d < DI) {
                    Ap[u] = g_Aexp + (((size_t)dir * DEPTH + l) * DI + d) * DS;
                    A0[u] = Ap[u][0];
                    flag[u] = g_Aflag[((size_t)dir * DEPTH + l) * DI + d];
#pragma unroll
                    for (int j = 0; j < DR; j++) wdt[u][j] = __ldg(dtw_l + (size_t)d * DR + j);
                    db0[u] = dtb_l[d];
                }
            }
            for (int cc = 0; cc < c; cc++) {
#pragma unroll
                for (int u = 0; u < 2; u++) {
                    int d = tid + u * 256;
                    if (d < DI) {
                        float Sc = g_S[(cb0 + cc) * DI + d];
                        if (flag[u]) {
                            float e = __expf(A0[u] * Sc);
                            float p = e;
#pragma unroll
                            for (int n = 0; n < DS; n++) {
                                g[u][n] = fmaf(p, g[u][n],
                                               g_hloc[((cb0 + cc) * DS + n) * DI + d]);
                                p *= e;
                            }
                        } else {
#pragma unroll
                            for (int n = 0; n < DS; n++)
                                g[u][n] = fmaf(__expf(__ldg(Ap[u] + n) * Sc), g[u][n],
                                               g_hloc[((cb0 + cc) * DS + n) * DI + d]);
                        }
                    }
                }
            }
            if (tid < 11)
                ((float4*)sm)[tid] = __ldg((const float4*)(g_dbl + (r0 + t0) * XD) + tid);
            __syncthreads();
            for (int t = t0; t < t1; t++) {
                const float* cur = sm + (t & 1) * 44;
                if (t + 1 < t1 && tid < 11)
                    ((float4*)(sm + ((t + 1) & 1) * 44))[tid] =
                        __ldg((const float4*)(g_dbl + (r0 + t + 1) * XD) + tid);
#pragma unroll
                for (int u = 0; u < 2; u++) {
                    int d = tid + u * 256;
                    if (d < DI) {
                        float dtr = db0[u];
#pragma unroll
                        for (int j = 0; j < DR; j++) dtr = fmaf(cur[j], wdt[u][j], dtr);
                        float dt = softplusf(dtr);
                        float acc = 0.f;
                        if (flag[u]) {
                            float e = __expf(dt * A0[u]);
                            float p = e;
#pragma unroll
                            for (int n = 0; n < DS; n++) {
                                g[u][n] *= p;
                                acc = fmaf(g[u][n], cur[28 + n], acc);
                                p *= e;
                            }
                        } else {
#pragma unroll
                            for (int n = 0; n < DS; n++) {
                                g[u][n] *= __expf(dt * __ldg(Ap[u] + n));
                                acc = fmaf(g[u][n], cur[28 + n], acc);
                            }
                        }
                        g_y[(r0 + t) * DI + d] += acc;
                    }
                }
                __syncthreads();
            }
        }
        gbar(++gen);

        // ---- S7: out_proj GEMM (gated A) + residual add + rmsnorm -----------
        {
            float* As = sm;                  // [16][12]
            float* Ws = sm + 16 * 12;        // [16][196]
            for (int tile = bid; tile < 201; tile += NBLK) {
                int row0 = tile * 8;
                float acc[6] = {0.f, 0.f, 0.f, 0.f, 0.f, 0.f};
                for (int k0 = 0; k0 < DI; k0 += 16) {
                    if (tid < 32) {
                        int m = tid >> 2, kq = tid & 3;
                        int r = row0 + m;
                        float4 a = make_float4(0.f, 0.f, 0.f, 0.f);
                        if (r < ROWS) {
                            int b = r / LSEQ, t = r % LSEQ;
                            int d0 = k0 + kq * 4;
                            float4 yf = __ldg((const float4*)(g_y + (size_t)r * DI + d0));
                            size_t rb = ((size_t)(BATCH + b) * LSEQ + (LSEQ - 1 - t));
                            float4 yb = __ldg((const float4*)(g_y + rb * DI + d0));
                            float4 z4 = __ldg((const float4*)(g_xz + (size_t)r * 2 * DI + DI + d0));
                            a.x = (yf.x + yb.x) * siluf(z4.x);
                            a.y = (yf.y + yb.y) * siluf(z4.y);
                            a.z = (yf.z + yb.z) * siluf(z4.z);
                            a.w = (yf.w + yb.w) * siluf(z4.w);
                        }
                        As[(kq * 4 + 0) * 12 + m] = a.x; As[(kq * 4 + 1) * 12 + m] = a.y;
                        As[(kq * 4 + 2) * 12 + m] = a.z; As[(kq * 4 + 3) * 12 + m] = a.w;
                    }
                    for (int i = tid; i < 768; i += 256) {
                        int n = i >> 2, kq = i & 3;
                        float4 v = __ldg((const float4*)(opw_l + (size_t)n * DI + k0 + kq * 4));
                        Ws[(kq * 4 + 0) * 196 + n] = v.x; Ws[(kq * 4 + 1) * 196 + n] = v.y;
                        Ws[(kq * 4 + 2) * 196 + n] = v.z; Ws[(kq * 4 + 3) * 196 + n] = v.w;
                    }
                    __syncthreads();
                    int ty = tid >> 5, tx = tid & 31;
#pragma unroll
                    for (int k = 0; k < 16; k++) {
                        float ra = As[k * 12 + ty];
#pragma unroll
                        for (int j = 0; j < 6; j++)
                            acc[j] = fmaf(ra, Ws[k * 196 + tx * 6 + j], acc[j]);
                    }
                    __syncthreads();
                }
                // epilogue: one warp owns one full row of 192
                int ty = tid >> 5, tx = tid & 31;
                int r = row0 + ty;
                bool valid = (r < ROWS);
                float v[6];
                float s = 0.f;
                if (valid) {
#pragma unroll
                    for (int j = 0; j < 6; j++) {
                        v[j] = g_res[(size_t)r * DM + tx * 6 + j] + acc[j];
                        s += v[j] * v[j];
                    }
                }
#pragma unroll
                for (int ofs = 16; ofs > 0; ofs >>= 1)
                    s += __shfl_xor_sync(0xffffffffu, s, ofs);
                float rs = rsqrtf(s / (float)DM + EPSV);
                if (valid) {
#pragma unroll
                    for (int j = 0; j < 6; j++) {
                        int cc = tx * 6 + j;
                        g_res[(size_t)r * DM + cc] = v[j];
                        g_hn[(size_t)r * DM + cc] = v[j] * rs * __ldg(nw_next + cc);
                    }
                }
            }
        }
        gbar(++gen);
    }

    // ================= final head =============================================
    if (bid == 0 && tid < BATCH * NCLS) {
        int b = tid / NCLS, c = tid % NCLS;
        const float* row = g_hn + (size_t)b * LSEQ * DM;   // token 0, already normed
        float acc = hb[c];
        for (int j = 0; j < DM; j++) acc = fmaf(row[j], hw[(size_t)c * DM + j], acc);
        out[b * NCLS + c] = acc;
    }
}

// ---------------- host --------------------------------------------------------
extern "C" void kernel_launch(void* const* d_in, const int* in_sizes, int n_in,
                              void* d_out, int out_size) {
    (void)in_sizes; (void)n_in; (void)out_size;
    const float* x      = (const float*)d_in[0];
    const float* pe_w   = (const float*)d_in[1];
    const float* pe_b   = (const float*)d_in[2];
    const float* cls    = (const float*)d_in[3];
    const float* pos    = (const float*)d_in[4];
    const float* norm_w = (const float*)d_in[5];
    const float* ipw    = (const float*)d_in[6];
    const float* cw     = (const float*)d_in[7];
    const float* cb     = (const float*)d_in[8];
    const float* xpw    = (const float*)d_in[9];
    const float* dtw    = (const float*)d_in[10];
    const float* dtb    = (const float*)d_in[11];
    const float* Alog   = (const float*)d_in[12];
    const float* Ablog  = (const float*)d_in[13];
    const float* Dp     = (const float*)d_in[14];
    const float* opw    = (const float*)d_in[15];
    const float* nfw    = (const float*)d_in[16];
    const float* hw     = (const float*)d_in[17];
    const float* hb     = (const float*)d_in[18];
    float* out = (float*)d_out;

    k_prepA<<<(2 * DEPTH * DI + 127) / 128, 128>>>(Alog, Ablog);
    k_net<<<NBLK, 256>>>(x, pe_w, pe_b, cls, pos, norm_w, ipw, cw, cb, xpw,
                         dtw, dtb, Dp, opw, nfw, hw, hb, out);
}

// round 6
// speedup vs baseline: 1.2340x; 1.2340x over previous
#include <cuda_runtime.h>
#include <math.h>

#define DEPTH 24
#define DM    192
#define DI    384
#define DS    16
#define DR    12
#define BATCH 4
#define LSEQ  401
#define NCLS  22
#define XD    44
#define EPSV  1e-5f
#define NC    31
#define CL    13
#define ROWS  (BATCH*LSEQ)     // 1604
#define ROWS2 (2*BATCH*LSEQ)   // 3208
#define NBLK  296

// ---------------- scratch ----------------------------------------------------
__device__ float g_res [ROWS*DM];
__device__ float g_hn  [ROWS*DM];
__device__ float g_xz  [ROWS*2*DI];
__device__ float g_xx  [ROWS2*DI];
__device__ float g_dt  [ROWS2*DI];
__device__ float g_dbl [ROWS2*XD];
__device__ float g_y   [ROWS2*DI];
__device__ float g_Aexp[2*DEPTH*DI*DS];
__device__ int   g_Aflag[2*DEPTH*DI];
__device__ float g_hloc[2*BATCH*NC*DS*DI];
__device__ float g_S   [2*BATCH*NC*DI];
__device__ volatile int g_arrive[NBLK];
__device__ volatile int g_release;

__device__ __forceinline__ float siluf(float x) { return x / (1.f + __expf(-x)); }
__device__ __forceinline__ float softplusf(float x) {
    return x > 20.f ? x : log1pf(__expf(x));
}

// ------- deterministic global barrier: gens 1..N, reset at kernel end --------
__device__ __forceinline__ void gbar(int gen) {
    __syncthreads();
    if (blockIdx.x == 0) {
        for (int i = threadIdx.x; i < NBLK; i += 256) {
            if (i == 0) continue;
            while (g_arrive[i] < gen) __nanosleep(40);
        }
        __threadfence();
        __syncthreads();
        if (threadIdx.x == 0) g_release = gen;
    } else {
        if (threadIdx.x == 0) {
            __threadfence();
            g_arrive[blockIdx.x] = gen;
            while (g_release < gen) __nanosleep(40);
            __threadfence();
        }
        __syncthreads();
    }
}

// ---------------- prep: A = -exp(A_log); detect geometric structure ----------
__global__ void k_prepA(const float* __restrict__ Alog, const float* __restrict__ Ablog) {
    int i = blockIdx.x * blockDim.x + threadIdx.x;
    if (i >= 2 * DEPTH * DI) return;
    int dir = i / (DEPTH * DI);
    int rest = i - dir * (DEPTH * DI);
    const float* src = (dir ? Ablog : Alog) + (size_t)rest * DS;
    float A[DS];
#pragma unroll
    for (int n = 0; n < DS; n++) A[n] = -__expf(src[n]);
    float A0 = A[0];
    bool ok = true;
#pragma unroll
    for (int n = 1; n < DS; n++) {
        float tgt = (float)(n + 1) * A0;
        ok = ok && (fabsf(A[n] - tgt) <= 1e-4f * fabsf(tgt) + 1e-30f);
    }
#pragma unroll
    for (int n = 0; n < DS; n++) g_Aexp[(size_t)i * DS + n] = A[n];
    g_Aflag[i] = ok ? 1 : 0;
}

// =============================================================================
// Whole network, one persistent kernel, 5 barriers/layer.
// =============================================================================
__global__ __launch_bounds__(256, 2)
void k_net(const float* __restrict__ x,   const float* __restrict__ pew,
           const float* __restrict__ peb, const float* __restrict__ cls,
           const float* __restrict__ pos, const float* __restrict__ norm_w,
           const float* __restrict__ ipw, const float* __restrict__ cw,
           const float* __restrict__ cb,  const float* __restrict__ xpw,
           const float* __restrict__ dtw, const float* __restrict__ dtb,
           const float* __restrict__ Dp,  const float* __restrict__ opw,
           const float* __restrict__ nfw, const float* __restrict__ hw,
           const float* __restrict__ hb,  float* __restrict__ out) {
    const int bid = blockIdx.x;
    const int tid = threadIdx.x;
    int gen = 0;
    __shared__ float sm[7424];
    __shared__ float red2[8];

    // ===== stage E: patch embed + cls + pos + layer-0 residual/norm ==========
    for (int p = bid; p < ROWS; p += NBLK) {
        int b = p / LSEQ, t = p % LSEQ;
        float v = 0.f;
        if (t == 0) {
            if (tid < DM) v = cls[tid] + pos[tid];
        } else {
            int pp = t - 1, ph = pp / 200, pw = pp % 200;
            sm[tid] = x[(size_t)b * 32 * 3200 + (size_t)(ph * 16 + tid / 16) * 3200
                        + pw * 16 + (tid % 16)];
            __syncthreads();
            if (tid < DM) {
                float acc = peb[tid];
                const float* wc = pew + (size_t)tid * 256;
#pragma unroll 8
                for (int i = 0; i < 256; i++) acc = fmaf(sm[i], __ldg(wc + i), acc);
                v = acc + pos[(size_t)t * DM + tid];
            }
        }
        float u = 2.f * v;
        float s = (tid < DM) ? u * u : 0.f;
#pragma unroll
        for (int ofs = 16; ofs > 0; ofs >>= 1) s += __shfl_xor_sync(0xffffffffu, s, ofs);
        if ((tid & 31) == 0 && tid < DM) red2[tid >> 5] = s;
        __syncthreads();
        if (tid < DM) {
            float tot = red2[0] + red2[1] + red2[2] + red2[3] + red2[4] + red2[5];
            float rs = rsqrtf(tot / (float)DM + EPSV);
            size_t o = (size_t)p * DM + tid;
            g_res[o] = u;
            g_hn[o]  = u * rs * norm_w[tid];
        }
        __syncthreads();
    }
    gbar(++gen);

    // ===== layer loop =========================================================
    for (int l = 0; l < DEPTH; l++) {
        const float* ipw_l = ipw + (size_t)l * 2 * DI * DM;
        const float* cw_l  = cw  + (size_t)l * DI * 4;
        const float* cb_l  = cb  + (size_t)l * DI;
        const float* xpw_l = xpw + (size_t)l * XD * DI;
        const float* dtw_l = dtw + (size_t)l * DI * DR;
        const float* dtb_l = dtb + (size_t)l * DI;
        const float* Dp_l  = Dp  + (size_t)l * DI;
        const float* opw_l = opw + (size_t)l * DM * DI;
        const float* nw_next = (l == DEPTH - 1) ? nfw : (norm_w + (size_t)(l + 1) * DM);

        // ---- S2: in_proj GEMM  xz[1604,768] = hn @ ipw^T --------------------
        {
            float* As = sm;                  // [16][68]
            float* Ws = sm + 16 * 68;        // [16][68]
            for (int tile = bid; tile < 26 * 12; tile += NBLK) {
                int bx = tile % 12, by = tile / 12;
                int row0 = by * 64, col0 = bx * 64;
                float acc[4][4];
#pragma unroll
                for (int i = 0; i < 4; i++)
#pragma unroll
                    for (int j = 0; j < 4; j++) acc[i][j] = 0.f;
                int m = tid >> 2, kq = tid & 3;
                for (int k0 = 0; k0 < DM; k0 += 16) {
                    float4 va = make_float4(0.f, 0.f, 0.f, 0.f);
                    if (row0 + m < ROWS)
                        va = __ldg((const float4*)(g_hn + (size_t)(row0 + m) * DM + k0 + kq * 4));
                    As[(kq * 4 + 0) * 68 + m] = va.x; As[(kq * 4 + 1) * 68 + m] = va.y;
                    As[(kq * 4 + 2) * 68 + m] = va.z; As[(kq * 4 + 3) * 68 + m] = va.w;
                    float4 vw = __ldg((const float4*)(ipw_l + (size_t)(col0 + m) * DM + k0 + kq * 4));
                    Ws[(kq * 4 + 0) * 68 + m] = vw.x; Ws[(kq * 4 + 1) * 68 + m] = vw.y;
                    Ws[(kq * 4 + 2) * 68 + m] = vw.z; Ws[(kq * 4 + 3) * 68 + m] = vw.w;
                    __syncthreads();
                    int ty = tid / 16, tx = tid % 16;
#pragma unroll
                    for (int k = 0; k < 16; k++) {
                        float ra[4], rb[4];
#pragma unroll
                        for (int i = 0; i < 4; i++) ra[i] = As[k * 68 + ty * 4 + i];
#pragma unroll
                        for (int j = 0; j < 4; j++) rb[j] = Ws[k * 68 + tx * 4 + j];
#pragma unroll
                        for (int i = 0; i < 4; i++)
#pragma unroll
                            for (int j = 0; j < 4; j++)
                                acc[i][j] = fmaf(ra[i], rb[j], acc[i][j]);
                    }
                    __syncthreads();
                }
                int ty = tid / 16, tx = tid % 16;
#pragma unroll
                for (int i = 0; i < 4; i++) {
                    int r = row0 + ty * 4 + i;
                    if (r >= ROWS) continue;
#pragma unroll
                    for (int j = 0; j < 4; j++)
                        g_xz[(size_t)r * 2 * DI + col0 + tx * 4 + j] = acc[i][j];
                }
            }
        }
        gbar(++gen);

        // ---- S4: conv+silu (into smem + g_xx) then dbl GEMM -----------------
        {
            float* As = sm;                  // [384][17] transposed conv output
            float* Ws = sm + 384 * 17;       // [16][52]
            for (int tile = bid; tile < 201; tile += NBLK) {
                int row0 = tile * 16;
                // conv: 16 rows x 384 d, all 256 threads
                for (int idx = tid; idx < 16 * DI; idx += 256) {
                    int mm = idx / DI, d = idx - (idx / DI) * DI;
                    int r = row0 + mm;
                    if (r < ROWS2) {
                        int dir = r / ROWS;
                        int rem = r - dir * ROWS;
                        int b = rem / LSEQ, t = rem % LSEQ;
                        float4 w4 = __ldg((const float4*)(cw_l + d * 4));
                        float s = cb_l[d];
                        const float* xzb = g_xz + (size_t)b * LSEQ * 2 * DI + d;
                        if (dir == 0) {
                            if (t >= 3) s = fmaf(w4.x, xzb[(size_t)(t - 3) * 2 * DI], s);
                            if (t >= 2) s = fmaf(w4.y, xzb[(size_t)(t - 2) * 2 * DI], s);
                            if (t >= 1) s = fmaf(w4.z, xzb[(size_t)(t - 1) * 2 * DI], s);
                            s = fmaf(w4.w, xzb[(size_t)t * 2 * DI], s);
                        } else {
                            int base = LSEQ - 1 - t;
                            s = fmaf(w4.w, xzb[(size_t)base * 2 * DI], s);
                            if (t >= 1) s = fmaf(w4.z, xzb[(size_t)(base + 1) * 2 * DI], s);
                            if (t >= 2) s = fmaf(w4.y, xzb[(size_t)(base + 2) * 2 * DI], s);
                            if (t >= 3) s = fmaf(w4.x, xzb[(size_t)(base + 3) * 2 * DI], s);
                        }
                        float xv = siluf(s);
                        As[d * 17 + mm] = xv;
                        g_xx[(size_t)r * DI + d] = xv;
                    } else {
                        As[d * 17 + mm] = 0.f;
                    }
                }
                __syncthreads();
                // GEMM: dbl[16 rows, 44] += As^T @ xpw^T
                float acc[3] = {0.f, 0.f, 0.f};
                int ty = tid / 16, tx = tid % 16;
                for (int k0 = 0; k0 < DI; k0 += 16) {
                    if (tid < 176) {
                        int n = tid >> 2, kq = tid & 3;
                        float4 v = __ldg((const float4*)(xpw_l + (size_t)n * DI + k0 + kq * 4));
                        Ws[(kq * 4 + 0) * 52 + n] = v.x; Ws[(kq * 4 + 1) * 52 + n] = v.y;
                        Ws[(kq * 4 + 2) * 52 + n] = v.z; Ws[(kq * 4 + 3) * 52 + n] = v.w;
                    }
                    __syncthreads();
#pragma unroll
                    for (int k = 0; k < 16; k++) {
                        float ra = As[(k0 + k) * 17 + ty];
#pragma unroll
                        for (int j = 0; j < 3; j++)
                            acc[j] = fmaf(ra, Ws[k * 52 + tx * 3 + j], acc[j]);
                    }
                    __syncthreads();
                }
                int r = row0 + ty;
                if (r < ROWS2) {
#pragma unroll
                    for (int j = 0; j < 3; j++) {
                        int n = tx * 3 + j;
                        if (n < XD) g_dbl[(size_t)r * XD + n] = acc[j];
                    }
                }
                __syncthreads();
            }
        }
        gbar(++gen);

        // ---- S5: scanA (chunk-local; dt_proj fused; stores dt) --------------
        if (bid < 2 * BATCH * NC) {
            int dir = bid / (BATCH * NC);
            int rem = bid - dir * (BATCH * NC);
            int b = rem / NC, c = rem % NC;
            size_t r0 = ((size_t)dir * BATCH + b) * LSEQ;
            int t0 = c * CL, t1 = min(LSEQ, t0 + CL);

#pragma unroll
            for (int u = 0; u < 2; u++) {
                int d = tid + u * 256;
                if (d >= DI) break;
                const float* Ap = g_Aexp + (((size_t)dir * DEPTH + l) * DI + d) * DS;
                float A0 = Ap[0];
                int flag = g_Aflag[((size_t)dir * DEPTH + l) * DI + d];
                float wdt[DR];
#pragma unroll
                for (int j = 0; j < DR; j++) wdt[j] = __ldg(dtw_l + (size_t)d * DR + j);
                float db0 = dtb_l[d], Dd = Dp_l[d];
                float h[DS];
#pragma unroll
                for (int n = 0; n < DS; n++) h[n] = 0.f;
                float S = 0.f;

                for (int t = t0; t < t1; t++) {
                    size_t r = r0 + t;
                    const float4* dbq = (const float4*)(g_dbl + r * XD);
                    float4 q0 = __ldg(dbq + 0), q1 = __ldg(dbq + 1), q2 = __ldg(dbq + 2);
                    float4 qB0 = __ldg(dbq + 3), qB1 = __ldg(dbq + 4),
                           qB2 = __ldg(dbq + 5), qB3 = __ldg(dbq + 6);
                    float4 qC0 = __ldg(dbq + 7), qC1 = __ldg(dbq + 8),
                           qC2 = __ldg(dbq + 9), qC3 = __ldg(dbq + 10);
                    float d1 = db0, d2 = 0.f;
                    d1 = fmaf(q0.x, wdt[0], d1); d2 = fmaf(q0.y, wdt[1], d2);
                    d1 = fmaf(q0.z, wdt[2], d1); d2 = fmaf(q0.w, wdt[3], d2);
                    d1 = fmaf(q1.x, wdt[4], d1); d2 = fmaf(q1.y, wdt[5], d2);
                    d1 = fmaf(q1.z, wdt[6], d1); d2 = fmaf(q1.w, wdt[7], d2);
                    d1 = fmaf(q2.x, wdt[8], d1); d2 = fmaf(q2.y, wdt[9], d2);
                    d1 = fmaf(q2.z, wdt[10], d1); d2 = fmaf(q2.w, wdt[11], d2);
                    float dt = softplusf(d1 + d2);
                    g_dt[r * DI + d] = dt;
                    float xv = g_xx[r * DI + d];
                    float dtx = dt * xv;
                    S += dt;
                    float Bv[DS] = {qB0.x, qB0.y, qB0.z, qB0.w, qB1.x, qB1.y, qB1.z, qB1.w,
                                    qB2.x, qB2.y, qB2.z, qB2.w, qB3.x, qB3.y, qB3.z, qB3.w};
                    float Cv[DS] = {qC0.x, qC0.y, qC0.z, qC0.w, qC1.x, qC1.y, qC1.z, qC1.w,
                                    qC2.x, qC2.y, qC2.z, qC2.w, qC3.x, qC3.y, qC3.z, qC3.w};
                    float acc = 0.f;
                    if (flag) {
                        float e = __expf(dt * A0);
                        float p = e;
#pragma unroll
                        for (int n = 0; n < DS; n++) {
                            h[n] = fmaf(p, h[n], dtx * Bv[n]);
                            acc = fmaf(h[n], Cv[n], acc);
                            p *= e;
                        }
                    } else {
#pragma unroll
                        for (int n = 0; n < DS; n++) {
                            float a = __expf(dt * __ldg(Ap + n));
                            h[n] = fmaf(a, h[n], dtx * Bv[n]);
                            acc = fmaf(h[n], Cv[n], acc);
                        }
                    }
                    g_y[r * DI + d] = acc + xv * Dd;
                }
                size_t cb_ = ((size_t)dir * BATCH + b) * NC + c;
#pragma unroll
                for (int n = 0; n < DS; n++) g_hloc[(cb_ * DS + n) * DI + d] = h[n];
                g_S[cb_ * DI + d] = S;
            }
        }
        gbar(++gen);

        // ---- S6: scanC (carry reconstruction + fixup; loads dt) -------------
        if (bid < 2 * BATCH * (NC - 1)) {
            int dir = bid / (BATCH * (NC - 1));
            int rem = bid - dir * (BATCH * (NC - 1));
            int b = rem / (NC - 1), c = rem % (NC - 1) + 1;
            size_t r0 = ((size_t)dir * BATCH + b) * LSEQ;
            size_t cb0 = ((size_t)dir * BATCH + b) * NC;
            int t0 = c * CL, t1 = min(LSEQ, t0 + CL);

#pragma unroll
            for (int u = 0; u < 2; u++) {
                int d = tid + u * 256;
                if (d >= DI) break;
                const float* Ap = g_Aexp + (((size_t)dir * DEPTH + l) * DI + d) * DS;
                float A0 = Ap[0];
                int flag = g_Aflag[((size_t)dir * DEPTH + l) * DI + d];
                float g[DS];
#pragma unroll
                for (int n = 0; n < DS; n++) g[n] = 0.f;
                for (int cc = 0; cc < c; cc++) {
                    float Sc = g_S[(cb0 + cc) * DI + d];
                    if (flag) {
                        float e = __expf(A0 * Sc);
                        float p = e;
#pragma unroll
                        for (int n = 0; n < DS; n++) {
                            g[n] = fmaf(p, g[n], g_hloc[((cb0 + cc) * DS + n) * DI + d]);
                            p *= e;
                        }
                    } else {
#pragma unroll
                        for (int n = 0; n < DS; n++)
                            g[n] = fmaf(__expf(__ldg(Ap + n) * Sc), g[n],
                                        g_hloc[((cb0 + cc) * DS + n) * DI + d]);
                    }
                }
                for (int t = t0; t < t1; t++) {
                    size_t r = r0 + t;
                    const float4* dbq = (const float4*)(g_dbl + r * XD);
                    float4 qC0 = __ldg(dbq + 7), qC1 = __ldg(dbq + 8),
                           qC2 = __ldg(dbq + 9), qC3 = __ldg(dbq + 10);
                    float dt = g_dt[r * DI + d];
                    float Cv[DS] = {qC0.x, qC0.y, qC0.z, qC0.w, qC1.x, qC1.y, qC1.z, qC1.w,
                                    qC2.x, qC2.y, qC2.z, qC2.w, qC3.x, qC3.y, qC3.z, qC3.w};
                    float acc = 0.f;
                    if (flag) {
                        float e = __expf(dt * A0);
                        float p = e;
#pragma unroll
                        for (int n = 0; n < DS; n++) {
                            g[n] *= p;
                            acc = fmaf(g[n], Cv[n], acc);
                            p *= e;
                        }
                    } else {
#pragma unroll
                        for (int n = 0; n < DS; n++) {
                            g[n] *= __expf(dt * __ldg(Ap + n));
                            acc = fmaf(g[n], Cv[n], acc);
                        }
                    }
                    g_y[r * DI + d] += acc;
                }
            }
        }
        gbar(++gen);

        // ---- S7: out_proj GEMM (gated A) + residual + rmsnorm ---------------
        {
            float* As = sm;                  // [16][12]
            float* Ws = sm + 16 * 12;        // [16][196]
            for (int tile = bid; tile < 201; tile += NBLK) {
                int row0 = tile * 8;
                float acc[6] = {0.f, 0.f, 0.f, 0.f, 0.f, 0.f};
                for (int k0 = 0; k0 < DI; k0 += 16) {
                    if (tid < 32) {
                        int m = tid >> 2, kq = tid & 3;
                        int r = row0 + m;
                        float4 a = make_float4(0.f, 0.f, 0.f, 0.f);
                        if (r < ROWS) {
                            int b = r / LSEQ, t = r % LSEQ;
                            int d0 = k0 + kq * 4;
                            float4 yf = __ldg((const float4*)(g_y + (size_t)r * DI + d0));
                            size_t rb = ((size_t)(BATCH + b) * LSEQ + (LSEQ - 1 - t));
                            float4 yb = __ldg((const float4*)(g_y + rb * DI + d0));
                            float4 z4 = __ldg((const float4*)(g_xz + (size_t)r * 2 * DI + DI + d0));
                            a.x = (yf.x + yb.x) * siluf(z4.x);
                            a.y = (yf.y + yb.y) * siluf(z4.y);
                            a.z = (yf.z + yb.z) * siluf(z4.z);
                            a.w = (yf.w + yb.w) * siluf(z4.w);
                        }
                        As[(kq * 4 + 0) * 12 + m] = a.x; As[(kq * 4 + 1) * 12 + m] = a.y;
                        As[(kq * 4 + 2) * 12 + m] = a.z; As[(kq * 4 + 3) * 12 + m] = a.w;
                    }
                    for (int i = tid; i < 768; i += 256) {
                        int n = i >> 2, kq = i & 3;
                        float4 v = __ldg((const float4*)(opw_l + (size_t)n * DI + k0 + kq * 4));
                        Ws[(kq * 4 + 0) * 196 + n] = v.x; Ws[(kq * 4 + 1) * 196 + n] = v.y;
                        Ws[(kq * 4 + 2) * 196 + n] = v.z; Ws[(kq * 4 + 3) * 196 + n] = v.w;
                    }
                    __syncthreads();
                    int ty = tid >> 5, tx = tid & 31;
#pragma unroll
                    for (int k = 0; k < 16; k++) {
                        float ra = As[k * 12 + ty];
#pragma unroll
                        for (int j = 0; j < 6; j++)
                            acc[j] = fmaf(ra, Ws[k * 196 + tx * 6 + j], acc[j]);
                    }
                    __syncthreads();
                }
                int ty = tid >> 5, tx = tid & 31;
                int r = row0 + ty;
                bool valid = (r < ROWS);
                float v[6];
                float s = 0.f;
                if (valid) {
#pragma unroll
                    for (int j = 0; j < 6; j++) {
                        v[j] = g_res[(size_t)r * DM + tx * 6 + j] + acc[j];
                        s += v[j] * v[j];
                    }
                }
#pragma unroll
                for (int ofs = 16; ofs > 0; ofs >>= 1)
                    s += __shfl_xor_sync(0xffffffffu, s, ofs);
                float rs = rsqrtf(s / (float)DM + EPSV);
                if (valid) {
#pragma unroll
                    for (int j = 0; j < 6; j++) {
                        int cc = tx * 6 + j;
                        g_res[(size_t)r * DM + cc] = v[j];
                        g_hn[(size_t)r * DM + cc] = v[j] * rs * __ldg(nw_next + cc);
                    }
                }
                __syncthreads();
            }
        }
        if (l < DEPTH - 1) gbar(++gen);
    }

    // ===== final: arrive-only barrier; block0 gathers, computes head, resets =
    ++gen;
    __syncthreads();
    if (bid != 0) {
        if (tid == 0) {
            __threadfence();
            g_arrive[bid] = gen;
        }
        return;
    }
    // block 0: gather all arrivals
    for (int i = tid; i < NBLK; i += 256) {
        if (i == 0) continue;
        while (g_arrive[i] < gen) __nanosleep(40);
    }
    __threadfence();
    __syncthreads();
    if (tid < BATCH * NCLS) {
        int b = tid / NCLS, c = tid % NCLS;
        const float* row = g_hn + (size_t)b * LSEQ * DM;   // token 0, already normed
        float acc = hb[c];
        for (int j = 0; j < DM; j++) acc = fmaf(row[j], hw[(size_t)c * DM + j], acc);
        out[b * NCLS + c] = acc;
    }
    __syncthreads();
    // reset barrier state for the next graph replay
    for (int i = tid; i < NBLK; i += 256) g_arrive[i] = 0;
    __syncthreads();
    if (tid == 0) g_release = 0;
}

// ---------------- host --------------------------------------------------------
extern "C" void kernel_launch(void* const* d_in, const int* in_sizes, int n_in,
                              void* d_out, int out_size) {
    (void)in_sizes; (void)n_in; (void)out_size;
    const float* x      = (const float*)d_in[0];
    const float* pe_w   = (const float*)d_in[1];
    const float* pe_b   = (const float*)d_in[2];
    const float* cls    = (const float*)d_in[3];
    const float* pos    = (const float*)d_in[4];
    const float* norm_w = (const float*)d_in[5];
    const float* ipw    = (const float*)d_in[6];
    const float* cw     = (const float*)d_in[7];
    const float* cb     = (const float*)d_in[8];
    const float* xpw    = (const float*)d_in[9];
    const float* dtw    = (const float*)d_in[10];
    const float* dtb    = (const float*)d_in[11];
    const float* Alog   = (const float*)d_in[12];
    const float* Ablog  = (const float*)d_in[13];
    const float* Dp     = (const float*)d_in[14];
    const float* opw    = (const float*)d_in[15];
    const float* nfw    = (const float*)d_in[16];
    const float* hw     = (const float*)d_in[17];
    const float* hb     = (const float*)d_in[18];
    float* out = (float*)d_out;

    k_prepA<<<(2 * DEPTH * DI + 127) / 128, 128>>>(Alog, Ablog);
    k_net<<<NBLK, 256>>>(x, pe_w, pe_b, cls, pos, norm_w, ipw, cw, cb, xpw,
                         dtw, dtb, Dp, opw, nfw, hw, hb, out);
}